// round 1
// baseline (speedup 1.0000x reference)
#include <cuda_runtime.h>
#include <cuda_bf16.h>
#include <math_constants.h>

// Problem constants
#define B_  2
#define S_  2048
#define D_  1024
#define H_  16
#define HD_ 64

// Scratch for Q,K,V in [B,H,S,HD] layout (no cudaMalloc allowed)
__device__ float g_Q[B_ * H_ * S_ * HD_];
__device__ float g_K[B_ * H_ * S_ * HD_];
__device__ float g_V[B_ * H_ * S_ * HD_];

// ---------------------------------------------------------------------------
// QKV projection: C = X @ W + b, output scattered to [B,H,S,HD]
// Classic 128x128x8 SGEMM, 256 threads, 8x8 microtile per thread.
// X: [4096, 1024] row-major, W: [1024, 1024] row-major.
// ---------------------------------------------------------------------------
__global__ __launch_bounds__(256) void qkv_gemm_kernel(
    const float* __restrict__ X,
    const float* __restrict__ W,
    const float* __restrict__ bias,
    float* __restrict__ out)  // [B,H,S,HD]
{
    __shared__ float As[8][128];   // transposed A tile: As[k][m]
    __shared__ float Bs[8][128];   // Bs[k][n]

    const int tid = threadIdx.x;
    const int m0 = blockIdx.y * 128;
    const int n0 = blockIdx.x * 128;

    const int aRow = tid >> 1;            // 0..127
    const int aCol = (tid & 1) * 4;       // 0 or 4
    const int bRow = tid >> 5;            // 0..7
    const int bCol = (tid & 31) * 4;      // 0..124

    const int ty = (tid >> 4) * 8;        // row offset of microtile
    const int tx = (tid & 15) * 8;        // col offset of microtile

    float acc[8][8];
#pragma unroll
    for (int i = 0; i < 8; i++)
#pragma unroll
        for (int j = 0; j < 8; j++) acc[i][j] = 0.0f;

    for (int kt = 0; kt < D_; kt += 8) {
        // Load A tile (transposed into As)
        float4 av = *(const float4*)&X[(m0 + aRow) * D_ + kt + aCol];
        As[aCol + 0][aRow] = av.x;
        As[aCol + 1][aRow] = av.y;
        As[aCol + 2][aRow] = av.z;
        As[aCol + 3][aRow] = av.w;
        // Load B tile
        *(float4*)&Bs[bRow][bCol] = *(const float4*)&W[(kt + bRow) * D_ + n0 + bCol];
        __syncthreads();

#pragma unroll
        for (int kk = 0; kk < 8; kk++) {
            float a[8], b[8];
            *(float4*)&a[0] = *(float4*)&As[kk][ty];
            *(float4*)&a[4] = *(float4*)&As[kk][ty + 4];
            *(float4*)&b[0] = *(float4*)&Bs[kk][tx];
            *(float4*)&b[4] = *(float4*)&Bs[kk][tx + 4];
#pragma unroll
            for (int i = 0; i < 8; i++)
#pragma unroll
                for (int j = 0; j < 8; j++)
                    acc[i][j] = fmaf(a[i], b[j], acc[i][j]);
        }
        __syncthreads();
    }

    // Write out with bias into [B,H,S,HD]
#pragma unroll
    for (int i = 0; i < 8; i++) {
        const int m = m0 + ty + i;      // global row = b*S + s
        const int b = m >> 11;          // /2048
        const int s = m & (S_ - 1);
#pragma unroll
        for (int j = 0; j < 8; j++) {
            const int n  = n0 + tx + j; // output feature
            const int h  = n >> 6;
            const int hd = n & 63;
            out[(((b * H_ + h) * S_) + s) * HD_ + hd] = acc[i][j] + bias[n];
        }
    }
}

// ---------------------------------------------------------------------------
// Flash-style attention: 1 CTA = (b, h, 64-row q tile), 256 threads (8 warps).
// Each warp owns 8 q-rows; each lane owns key/dim columns {lane, lane+32}.
// Streams 64-wide K/V tiles, online softmax, fp32 accumulation.
// smem: Qs, Ks, Vs, Ps each [64][68] (pad 68 -> conflict-free float4 rows).
// ---------------------------------------------------------------------------
#define TPAD 68
#define SMEM_FLOATS (4 * 64 * TPAD)

__global__ __launch_bounds__(256) void attn_kernel(
    const float* __restrict__ mask,   // [B,1,1,S]
    float* __restrict__ out)          // [B,S,D]
{
    extern __shared__ float sm[];
    float* Qs = sm;
    float* Ks = sm + 64 * TPAD;
    float* Vs = sm + 2 * 64 * TPAD;
    float* Ps = sm + 3 * 64 * TPAD;

    const int qt = blockIdx.x;   // 0..31
    const int h  = blockIdx.y;   // 0..15
    const int b  = blockIdx.z;   // 0..1

    const int tid  = threadIdx.x;
    const int w    = tid >> 5;
    const int lane = tid & 31;

    const long long headBase = ((long long)(b * H_ + h)) * S_ * HD_;
    const float* Qg = g_Q + headBase + (long long)qt * 64 * HD_;
    const float* Kg = g_K + headBase;
    const float* Vg = g_V + headBase;

    // Load Q tile (64x64) into padded smem
#pragma unroll
    for (int t = 0; t < 4; t++) {
        const int lin = tid + t * 256;          // float4 index 0..1023
        const int row = lin >> 4;
        const int c4  = (lin & 15) << 2;
        float4 v = *(const float4*)&Qg[row * HD_ + c4];
        Qs[row * TPAD + c4 + 0] = v.x;
        Qs[row * TPAD + c4 + 1] = v.y;
        Qs[row * TPAD + c4 + 2] = v.z;
        Qs[row * TPAD + c4 + 3] = v.w;
    }

    float m_i[8], l_i[8], acc0[8], acc1[8];
#pragma unroll
    for (int r = 0; r < 8; r++) {
        m_i[r] = -1e30f; l_i[r] = 0.0f; acc0[r] = 0.0f; acc1[r] = 0.0f;
    }

    const float* maskb = mask + b * S_;

    for (int kt = 0; kt < S_ / 64; kt++) {
        __syncthreads();   // previous tile fully consumed
        // Load K and V tiles
        const float* Kt = Kg + kt * 64 * HD_;
        const float* Vt = Vg + kt * 64 * HD_;
#pragma unroll
        for (int t = 0; t < 4; t++) {
            const int lin = tid + t * 256;
            const int row = lin >> 4;
            const int c4  = (lin & 15) << 2;
            float4 kv = *(const float4*)&Kt[row * HD_ + c4];
            Ks[row * TPAD + c4 + 0] = kv.x;
            Ks[row * TPAD + c4 + 1] = kv.y;
            Ks[row * TPAD + c4 + 2] = kv.z;
            Ks[row * TPAD + c4 + 3] = kv.w;
            float4 vv = *(const float4*)&Vt[row * HD_ + c4];
            Vs[row * TPAD + c4 + 0] = vv.x;
            Vs[row * TPAD + c4 + 1] = vv.y;
            Vs[row * TPAD + c4 + 2] = vv.z;
            Vs[row * TPAD + c4 + 3] = vv.w;
        }
        __syncthreads();

        // --- Scores: S = Q @ K^T, each lane -> 8 rows x cols {lane, lane+32}
        float s0[8], s1[8];
#pragma unroll
        for (int r = 0; r < 8; r++) { s0[r] = 0.0f; s1[r] = 0.0f; }

#pragma unroll
        for (int i4 = 0; i4 < 16; i4++) {
            float4 k0 = *(float4*)&Ks[lane * TPAD + i4 * 4];
            float4 k1 = *(float4*)&Ks[(lane + 32) * TPAD + i4 * 4];
#pragma unroll
            for (int r = 0; r < 8; r++) {
                float4 q = *(float4*)&Qs[(w * 8 + r) * TPAD + i4 * 4];
                s0[r] = fmaf(q.x, k0.x, s0[r]);
                s0[r] = fmaf(q.y, k0.y, s0[r]);
                s0[r] = fmaf(q.z, k0.z, s0[r]);
                s0[r] = fmaf(q.w, k0.w, s0[r]);
                s1[r] = fmaf(q.x, k1.x, s1[r]);
                s1[r] = fmaf(q.y, k1.y, s1[r]);
                s1[r] = fmaf(q.z, k1.z, s1[r]);
                s1[r] = fmaf(q.w, k1.w, s1[r]);
            }
        }

        const float msk0 = maskb[kt * 64 + lane];
        const float msk1 = maskb[kt * 64 + lane + 32];

        // --- Online softmax per row
#pragma unroll
        for (int r = 0; r < 8; r++) {
            float a0 = s0[r] * 0.125f + msk0;   // 1/sqrt(64)
            float a1 = s1[r] * 0.125f + msk1;
            float tmax = fmaxf(a0, a1);
#pragma unroll
            for (int off = 16; off > 0; off >>= 1)
                tmax = fmaxf(tmax, __shfl_xor_sync(0xFFFFFFFFu, tmax, off));
            const float mnew = fmaxf(m_i[r], tmax);
            const float corr = __expf(m_i[r] - mnew);
            const float p0 = __expf(a0 - mnew);
            const float p1 = __expf(a1 - mnew);
            float rs = p0 + p1;
#pragma unroll
            for (int off = 16; off > 0; off >>= 1)
                rs += __shfl_xor_sync(0xFFFFFFFFu, rs, off);
            l_i[r] = l_i[r] * corr + rs;
            m_i[r] = mnew;
            acc0[r] *= corr;
            acc1[r] *= corr;
            Ps[(w * 8 + r) * TPAD + lane]      = p0;
            Ps[(w * 8 + r) * TPAD + lane + 32] = p1;
        }
        __syncwarp();

        // --- O += P @ V, lane owns dims {lane, lane+32}
#pragma unroll
        for (int k4 = 0; k4 < 16; k4++) {
            float pr[8][4];
#pragma unroll
            for (int r = 0; r < 8; r++)
                *(float4*)&pr[r][0] = *(float4*)&Ps[(w * 8 + r) * TPAD + k4 * 4];
#pragma unroll
            for (int kk = 0; kk < 4; kk++) {
                const int k = k4 * 4 + kk;
                const float v0 = Vs[k * TPAD + lane];
                const float v1 = Vs[k * TPAD + lane + 32];
#pragma unroll
                for (int r = 0; r < 8; r++) {
                    acc0[r] = fmaf(pr[r][kk], v0, acc0[r]);
                    acc1[r] = fmaf(pr[r][kk], v1, acc1[r]);
                }
            }
        }
    }

    // --- Final normalize + write [B,S,D], d = h*64 + dim
#pragma unroll
    for (int r = 0; r < 8; r++) {
        const int q = qt * 64 + w * 8 + r;
        const float inv = 1.0f / l_i[r];
        float* dst = out + ((long long)(b * S_ + q)) * D_ + h * HD_;
        dst[lane]      = acc0[r] * inv;
        dst[lane + 32] = acc1[r] * inv;
    }
}

// ---------------------------------------------------------------------------
// Launch
// ---------------------------------------------------------------------------
extern "C" void kernel_launch(void* const* d_in, const int* in_sizes, int n_in,
                              void* d_out, int out_size)
{
    const float* hs   = (const float*)d_in[0];
    const float* mask = (const float*)d_in[1];
    const float* Wq   = (const float*)d_in[2];
    const float* bq   = (const float*)d_in[3];
    const float* Wk   = (const float*)d_in[4];
    const float* bk   = (const float*)d_in[5];
    const float* Wv   = (const float*)d_in[6];
    const float* bv   = (const float*)d_in[7];
    float* out = (float*)d_out;

    float *qp, *kp, *vp;
    cudaGetSymbolAddress((void**)&qp, g_Q);
    cudaGetSymbolAddress((void**)&kp, g_K);
    cudaGetSymbolAddress((void**)&vp, g_V);

    dim3 ggrid(D_ / 128, (B_ * S_) / 128);   // (8, 32)
    qkv_gemm_kernel<<<ggrid, 256>>>(hs, Wq, bq, qp);
    qkv_gemm_kernel<<<ggrid, 256>>>(hs, Wk, bk, kp);
    qkv_gemm_kernel<<<ggrid, 256>>>(hs, Wv, bv, vp);

    static bool attr_set = false;
    const int smem_bytes = SMEM_FLOATS * sizeof(float);  // 69632
    cudaFuncSetAttribute(attn_kernel, cudaFuncAttributeMaxDynamicSharedMemorySize,
                         smem_bytes);

    dim3 agrid(S_ / 64, H_, B_);             // (32, 16, 2)
    attn_kernel<<<agrid, 256, smem_bytes>>>(mask, out);
    (void)attr_set; (void)in_sizes; (void)n_in; (void)out_size;
}

// round 2
// speedup vs baseline: 1.0005x; 1.0005x over previous
#include <cuda_runtime.h>
#include <cuda_bf16.h>
#include <math_constants.h>

// Problem constants
#define B_  2
#define S_  2048
#define D_  1024
#define H_  16
#define HD_ 64

// Scratch for Q,K,V in [B,H,S,HD] layout (no cudaMalloc allowed)
__device__ float g_Q[B_ * H_ * S_ * HD_];
__device__ float g_K[B_ * H_ * S_ * HD_];
__device__ float g_V[B_ * H_ * S_ * HD_];

// ---------------------------------------------------------------------------
// QKV projection: C = X @ W + b, output scattered to [B,H,S,HD]
// Classic 128x128x8 SGEMM, 256 threads, 8x8 microtile per thread.
// X: [4096, 1024] row-major, W: [1024, 1024] row-major.
// ---------------------------------------------------------------------------
__global__ __launch_bounds__(256) void qkv_gemm_kernel(
    const float* __restrict__ X,
    const float* __restrict__ W,
    const float* __restrict__ bias,
    float* __restrict__ out)  // [B,H,S,HD]
{
    __shared__ float As[8][128];   // transposed A tile: As[k][m]
    __shared__ float Bs[8][128];   // Bs[k][n]

    const int tid = threadIdx.x;
    const int m0 = blockIdx.y * 128;
    const int n0 = blockIdx.x * 128;

    const int aRow = tid >> 1;            // 0..127
    const int aCol = (tid & 1) * 4;       // 0 or 4
    const int bRow = tid >> 5;            // 0..7
    const int bCol = (tid & 31) * 4;      // 0..124

    const int ty = (tid >> 4) * 8;        // row offset of microtile
    const int tx = (tid & 15) * 8;        // col offset of microtile

    float acc[8][8];
#pragma unroll
    for (int i = 0; i < 8; i++)
#pragma unroll
        for (int j = 0; j < 8; j++) acc[i][j] = 0.0f;

    for (int kt = 0; kt < D_; kt += 8) {
        // Load A tile (transposed into As)
        float4 av = *(const float4*)&X[(m0 + aRow) * D_ + kt + aCol];
        As[aCol + 0][aRow] = av.x;
        As[aCol + 1][aRow] = av.y;
        As[aCol + 2][aRow] = av.z;
        As[aCol + 3][aRow] = av.w;
        // Load B tile
        *(float4*)&Bs[bRow][bCol] = *(const float4*)&W[(kt + bRow) * D_ + n0 + bCol];
        __syncthreads();

#pragma unroll
        for (int kk = 0; kk < 8; kk++) {
            float a[8], b[8];
            *(float4*)&a[0] = *(float4*)&As[kk][ty];
            *(float4*)&a[4] = *(float4*)&As[kk][ty + 4];
            *(float4*)&b[0] = *(float4*)&Bs[kk][tx];
            *(float4*)&b[4] = *(float4*)&Bs[kk][tx + 4];
#pragma unroll
            for (int i = 0; i < 8; i++)
#pragma unroll
                for (int j = 0; j < 8; j++)
                    acc[i][j] = fmaf(a[i], b[j], acc[i][j]);
        }
        __syncthreads();
    }

    // Write out with bias into [B,H,S,HD]
#pragma unroll
    for (int i = 0; i < 8; i++) {
        const int m = m0 + ty + i;      // global row = b*S + s
        const int b = m >> 11;          // /2048
        const int s = m & (S_ - 1);
#pragma unroll
        for (int j = 0; j < 8; j++) {
            const int n  = n0 + tx + j; // output feature
            const int h  = n >> 6;
            const int hd = n & 63;
            out[(((b * H_ + h) * S_) + s) * HD_ + hd] = acc[i][j] + bias[n];
        }
    }
}

// ---------------------------------------------------------------------------
// Flash-style attention: 1 CTA = (b, h, 64-row q tile), 256 threads (8 warps).
// Each warp owns 8 q-rows; each lane owns key/dim columns {lane, lane+32}.
// Streams 64-wide K/V tiles, online softmax, fp32 accumulation.
// smem: Qs, Ks, Vs, Ps each [64][68] (pad 68 -> conflict-free float4 rows).
// ---------------------------------------------------------------------------
#define TPAD 68
#define SMEM_FLOATS (4 * 64 * TPAD)

__global__ __launch_bounds__(256) void attn_kernel(
    const float* __restrict__ mask,   // [B,1,1,S]
    float* __restrict__ out)          // [B,S,D]
{
    extern __shared__ float sm[];
    float* Qs = sm;
    float* Ks = sm + 64 * TPAD;
    float* Vs = sm + 2 * 64 * TPAD;
    float* Ps = sm + 3 * 64 * TPAD;

    const int qt = blockIdx.x;   // 0..31
    const int h  = blockIdx.y;   // 0..15
    const int b  = blockIdx.z;   // 0..1

    const int tid  = threadIdx.x;
    const int w    = tid >> 5;
    const int lane = tid & 31;

    const long long headBase = ((long long)(b * H_ + h)) * S_ * HD_;
    const float* Qg = g_Q + headBase + (long long)qt * 64 * HD_;
    const float* Kg = g_K + headBase;
    const float* Vg = g_V + headBase;

    // Load Q tile (64x64) into padded smem
#pragma unroll
    for (int t = 0; t < 4; t++) {
        const int lin = tid + t * 256;          // float4 index 0..1023
        const int row = lin >> 4;
        const int c4  = (lin & 15) << 2;
        float4 v = *(const float4*)&Qg[row * HD_ + c4];
        Qs[row * TPAD + c4 + 0] = v.x;
        Qs[row * TPAD + c4 + 1] = v.y;
        Qs[row * TPAD + c4 + 2] = v.z;
        Qs[row * TPAD + c4 + 3] = v.w;
    }

    float m_i[8], l_i[8], acc0[8], acc1[8];
#pragma unroll
    for (int r = 0; r < 8; r++) {
        m_i[r] = -1e30f; l_i[r] = 0.0f; acc0[r] = 0.0f; acc1[r] = 0.0f;
    }

    const float* maskb = mask + b * S_;

    for (int kt = 0; kt < S_ / 64; kt++) {
        __syncthreads();   // previous tile fully consumed
        // Load K and V tiles
        const float* Kt = Kg + kt * 64 * HD_;
        const float* Vt = Vg + kt * 64 * HD_;
#pragma unroll
        for (int t = 0; t < 4; t++) {
            const int lin = tid + t * 256;
            const int row = lin >> 4;
            const int c4  = (lin & 15) << 2;
            float4 kv = *(const float4*)&Kt[row * HD_ + c4];
            Ks[row * TPAD + c4 + 0] = kv.x;
            Ks[row * TPAD + c4 + 1] = kv.y;
            Ks[row * TPAD + c4 + 2] = kv.z;
            Ks[row * TPAD + c4 + 3] = kv.w;
            float4 vv = *(const float4*)&Vt[row * HD_ + c4];
            Vs[row * TPAD + c4 + 0] = vv.x;
            Vs[row * TPAD + c4 + 1] = vv.y;
            Vs[row * TPAD + c4 + 2] = vv.z;
            Vs[row * TPAD + c4 + 3] = vv.w;
        }
        __syncthreads();

        // --- Scores: S = Q @ K^T, each lane -> 8 rows x cols {lane, lane+32}
        float s0[8], s1[8];
#pragma unroll
        for (int r = 0; r < 8; r++) { s0[r] = 0.0f; s1[r] = 0.0f; }

#pragma unroll
        for (int i4 = 0; i4 < 16; i4++) {
            float4 k0 = *(float4*)&Ks[lane * TPAD + i4 * 4];
            float4 k1 = *(float4*)&Ks[(lane + 32) * TPAD + i4 * 4];
#pragma unroll
            for (int r = 0; r < 8; r++) {
                float4 q = *(float4*)&Qs[(w * 8 + r) * TPAD + i4 * 4];
                s0[r] = fmaf(q.x, k0.x, s0[r]);
                s0[r] = fmaf(q.y, k0.y, s0[r]);
                s0[r] = fmaf(q.z, k0.z, s0[r]);
                s0[r] = fmaf(q.w, k0.w, s0[r]);
                s1[r] = fmaf(q.x, k1.x, s1[r]);
                s1[r] = fmaf(q.y, k1.y, s1[r]);
                s1[r] = fmaf(q.z, k1.z, s1[r]);
                s1[r] = fmaf(q.w, k1.w, s1[r]);
            }
        }

        const float msk0 = maskb[kt * 64 + lane];
        const float msk1 = maskb[kt * 64 + lane + 32];

        // --- Online softmax per row
#pragma unroll
        for (int r = 0; r < 8; r++) {
            float a0 = s0[r] * 0.125f + msk0;   // 1/sqrt(64)
            float a1 = s1[r] * 0.125f + msk1;
            float tmax = fmaxf(a0, a1);
#pragma unroll
            for (int off = 16; off > 0; off >>= 1)
                tmax = fmaxf(tmax, __shfl_xor_sync(0xFFFFFFFFu, tmax, off));
            const float mnew = fmaxf(m_i[r], tmax);
            const float corr = __expf(m_i[r] - mnew);
            const float p0 = __expf(a0 - mnew);
            const float p1 = __expf(a1 - mnew);
            float rs = p0 + p1;
#pragma unroll
            for (int off = 16; off > 0; off >>= 1)
                rs += __shfl_xor_sync(0xFFFFFFFFu, rs, off);
            l_i[r] = l_i[r] * corr + rs;
            m_i[r] = mnew;
            acc0[r] *= corr;
            acc1[r] *= corr;
            Ps[(w * 8 + r) * TPAD + lane]      = p0;
            Ps[(w * 8 + r) * TPAD + lane + 32] = p1;
        }
        __syncwarp();

        // --- O += P @ V, lane owns dims {lane, lane+32}
#pragma unroll
        for (int k4 = 0; k4 < 16; k4++) {
            float pr[8][4];
#pragma unroll
            for (int r = 0; r < 8; r++)
                *(float4*)&pr[r][0] = *(float4*)&Ps[(w * 8 + r) * TPAD + k4 * 4];
#pragma unroll
            for (int kk = 0; kk < 4; kk++) {
                const int k = k4 * 4 + kk;
                const float v0 = Vs[k * TPAD + lane];
                const float v1 = Vs[k * TPAD + lane + 32];
#pragma unroll
                for (int r = 0; r < 8; r++) {
                    acc0[r] = fmaf(pr[r][kk], v0, acc0[r]);
                    acc1[r] = fmaf(pr[r][kk], v1, acc1[r]);
                }
            }
        }
    }

    // --- Final normalize + write [B,S,D], d = h*64 + dim
#pragma unroll
    for (int r = 0; r < 8; r++) {
        const int q = qt * 64 + w * 8 + r;
        const float inv = 1.0f / l_i[r];
        float* dst = out + ((long long)(b * S_ + q)) * D_ + h * HD_;
        dst[lane]      = acc0[r] * inv;
        dst[lane + 32] = acc1[r] * inv;
    }
}

// ---------------------------------------------------------------------------
// Launch
// ---------------------------------------------------------------------------
extern "C" void kernel_launch(void* const* d_in, const int* in_sizes, int n_in,
                              void* d_out, int out_size)
{
    const float* hs   = (const float*)d_in[0];
    const float* mask = (const float*)d_in[1];
    const float* Wq   = (const float*)d_in[2];
    const float* bq   = (const float*)d_in[3];
    const float* Wk   = (const float*)d_in[4];
    const float* bk   = (const float*)d_in[5];
    const float* Wv   = (const float*)d_in[6];
    const float* bv   = (const float*)d_in[7];
    float* out = (float*)d_out;

    float *qp, *kp, *vp;
    cudaGetSymbolAddress((void**)&qp, g_Q);
    cudaGetSymbolAddress((void**)&kp, g_K);
    cudaGetSymbolAddress((void**)&vp, g_V);

    dim3 ggrid(D_ / 128, (B_ * S_) / 128);   // (8, 32)
    qkv_gemm_kernel<<<ggrid, 256>>>(hs, Wq, bq, qp);
    qkv_gemm_kernel<<<ggrid, 256>>>(hs, Wk, bk, kp);
    qkv_gemm_kernel<<<ggrid, 256>>>(hs, Wv, bv, vp);

    static bool attr_set = false;
    const int smem_bytes = SMEM_FLOATS * sizeof(float);  // 69632
    cudaFuncSetAttribute(attn_kernel, cudaFuncAttributeMaxDynamicSharedMemorySize,
                         smem_bytes);

    dim3 agrid(S_ / 64, H_, B_);             // (32, 16, 2)
    attn_kernel<<<agrid, 256, smem_bytes>>>(mask, out);
    (void)attr_set; (void)in_sizes; (void)n_in; (void)out_size;
}

// round 4
// speedup vs baseline: 2.7866x; 2.7852x over previous
#include <cuda_runtime.h>
#include <cuda_fp16.h>
#include <cstdint>

#define LOG2E 1.4426950408889634f
#define SC2   0.18033688011112042f   // 0.125 * LOG2E
#define PSH   9.0f                   // prob scale 2^9 (cancels in normalization)

__device__ __forceinline__ uint32_t s2u(const void* p) {
    uint32_t a;
    asm("{ .reg .u64 t; cvta.to.shared.u64 t, %1; cvt.u32.u64 %0, t; }" : "=r"(a) : "l"(p));
    return a;
}
__device__ __forceinline__ void ldm4(uint32_t (&r)[4], uint32_t addr) {
    asm volatile("ldmatrix.sync.aligned.m8n8.x4.shared.b16 {%0,%1,%2,%3}, [%4];"
        : "=r"(r[0]), "=r"(r[1]), "=r"(r[2]), "=r"(r[3]) : "r"(addr));
}
__device__ __forceinline__ void mmaf16(float (&c)[4], const uint32_t (&a)[4],
                                       uint32_t b0, uint32_t b1) {
    asm volatile("mma.sync.aligned.m16n8k16.row.col.f32.f16.f16.f32 "
        "{%0,%1,%2,%3}, {%4,%5,%6,%7}, {%8,%9}, {%0,%1,%2,%3};"
        : "+f"(c[0]), "+f"(c[1]), "+f"(c[2]), "+f"(c[3])
        : "r"(a[0]), "r"(a[1]), "r"(a[2]), "r"(a[3]), "r"(b0), "r"(b1));
}
__device__ __forceinline__ void cpa16(uint32_t dst, const void* src) {
    asm volatile("cp.async.cg.shared.global [%0], [%1], 16;" :: "r"(dst), "l"(src));
}
#define CP_COMMIT() asm volatile("cp.async.commit_group;" ::: "memory")
#define CP_WAIT0()  asm volatile("cp.async.wait_group 0;" ::: "memory")
#define CP_WAIT1()  asm volatile("cp.async.wait_group 1;" ::: "memory")

__device__ __forceinline__ float ex2(float x) {
    float y; asm("ex2.approx.f32 %0, %1;" : "=f"(y) : "f"(x)); return y;
}
__device__ __forceinline__ uint32_t packh2(__half a, __half b) {
    __half2 t = __halves2half2(a, b);
    return *reinterpret_cast<uint32_t*>(&t);
}

// ---------------- device scratch (no cudaMalloc) ----------------
__device__ __align__(16) __half g_Xhi[4096 * 1024];
__device__ __align__(16) __half g_Xlo[4096 * 1024];
__device__ __align__(16) __half g_Wthi[3072 * 1024];
__device__ __align__(16) __half g_Wtlo[3072 * 1024];
__device__ __align__(16) __half g_Qhi[32 * 2048 * 64];
__device__ __align__(16) __half g_Qlo[32 * 2048 * 64];
__device__ __align__(16) __half g_Khi[32 * 2048 * 64];
__device__ __align__(16) __half g_Klo[32 * 2048 * 64];
__device__ __align__(16) __half g_Vhi[32 * 64 * 2048];  // transposed [bh][hd][s]
__device__ __align__(16) __half g_Vlo[32 * 64 * 2048];

// ---------------- prep ----------------
__global__ __launch_bounds__(256) void k_split_x(const float4* __restrict__ X) {
    int i = blockIdx.x * 256 + threadIdx.x;
    float4 v = X[i];
    __half h0 = __float2half_rn(v.x), h1 = __float2half_rn(v.y);
    __half h2 = __float2half_rn(v.z), h3 = __float2half_rn(v.w);
    ((uint32_t*)g_Xhi)[2 * i] = packh2(h0, h1);
    ((uint32_t*)g_Xhi)[2 * i + 1] = packh2(h2, h3);
    ((uint32_t*)g_Xlo)[2 * i] = packh2(__float2half_rn(v.x - __half2float(h0)),
                                       __float2half_rn(v.y - __half2float(h1)));
    ((uint32_t*)g_Xlo)[2 * i + 1] = packh2(__float2half_rn(v.z - __half2float(h2)),
                                           __float2half_rn(v.w - __half2float(h3)));
}

__global__ void k_transw(const float* __restrict__ Wq, const float* __restrict__ Wk,
                         const float* __restrict__ Wv) {
    __shared__ float t[32][33];
    int z = blockIdx.z;
    const float* W = (z == 0) ? Wq : (z == 1) ? Wk : Wv;
    int n0 = blockIdx.x * 32, k0 = blockIdx.y * 32;
    int tx = threadIdx.x, ty = threadIdx.y;
#pragma unroll
    for (int i = 0; i < 4; i++)
        t[ty + i * 8][tx] = W[(k0 + ty + i * 8) * 1024 + n0 + tx];
    __syncthreads();
#pragma unroll
    for (int i = 0; i < 4; i++) {
        int n = n0 + ty + i * 8, k = k0 + tx;
        float x = t[tx][ty + i * 8];
        __half hi = __float2half_rn(x);
        g_Wthi[(size_t)(z * 1024 + n) * 1024 + k] = hi;
        g_Wtlo[(size_t)(z * 1024 + n) * 1024 + k] =
            __float2half_rn(x - __half2float(hi));
    }
}

// ---------------- fused QKV GEMM (mma.sync fp16 split) ----------------
// C[4096 x 3072] = X @ [Wq|Wk|Wv] + bias. Tile 128x128, k-stage 32, 256 thr.
#define GSTR 40                       // halves per smem row (32 + 8 pad)
#define GTEN (128 * GSTR * 2)         // 10240 B per tensor
#define GSTG (4 * GTEN)               // 40960 B per stage
#define GSM  (2 * GSTG)               // 81920 B

__global__ __launch_bounds__(256) void k_gemm(
    const float* __restrict__ bq, const float* __restrict__ bk,
    const float* __restrict__ bv)
{
    extern __shared__ char sm[];
    uint32_t sb = s2u(sm);
    int tid = threadIdx.x, wid = tid >> 5, lane = tid & 31;
    int n0 = blockIdx.x * 128, m0 = blockIdx.y * 128;
    int wm = (wid & 3) * 32, wn = (wid >> 2) * 64;

    const __half* s0p = g_Xhi + (size_t)m0 * 1024;
    const __half* s1p = g_Xlo + (size_t)m0 * 1024;
    const __half* s2p = g_Wthi + (size_t)n0 * 1024;
    const __half* s3p = g_Wtlo + (size_t)n0 * 1024;

    float c[2][8][4];
#pragma unroll
    for (int i = 0; i < 2; i++)
#pragma unroll
        for (int t = 0; t < 8; t++)
#pragma unroll
            for (int r = 0; r < 4; r++) c[i][t][r] = 0.0f;

    auto load_stage = [&](int buf, int k0) {
#pragma unroll
        for (int t = 0; t < 8; t++) {
            int id = tid + t * 256;                 // 0..2047
            int tensor = id >> 9, within = id & 511;
            int row = within >> 2, c4 = within & 3;
            const __half* src = (tensor == 0 ? s0p : tensor == 1 ? s1p :
                                 tensor == 2 ? s2p : s3p) +
                                (size_t)row * 1024 + k0 + c4 * 8;
            uint32_t dst = sb + buf * GSTG + tensor * GTEN + row * (GSTR * 2) + c4 * 16;
            cpa16(dst, src);
        }
        CP_COMMIT();
    };

    load_stage(0, 0);
    int arow = lane & 15, asel = (lane >> 4) * 8;
    int q8 = lane >> 3, r8 = lane & 7;
    int brow = ((q8 >> 1) ? 8 : 0) + r8, bsel = (q8 & 1) * 8;

    for (int kc = 0; kc < 32; kc++) {
        if (kc + 1 < 32) { load_stage((kc + 1) & 1, (kc + 1) * 32); CP_WAIT1(); }
        else CP_WAIT0();
        __syncthreads();
        uint32_t base = sb + (kc & 1) * GSTG;
#pragma unroll
        for (int ks = 0; ks < 2; ks++) {
            int koff = ks * 16;
            uint32_t ahi[2][4], alo[2][4];
#pragma unroll
            for (int i = 0; i < 2; i++) {
                uint32_t ad = base + ((wm + i * 16 + arow) * GSTR + koff + asel) * 2;
                ldm4(ahi[i], ad);
                ldm4(alo[i], ad + GTEN);
            }
            uint32_t bhi[4][4], blo[4][4];
#pragma unroll
            for (int j = 0; j < 4; j++) {
                uint32_t bd = base + 2 * GTEN + ((wn + j * 16 + brow) * GSTR + koff + bsel) * 2;
                ldm4(bhi[j], bd);
                ldm4(blo[j], bd + GTEN);
            }
#pragma unroll
            for (int i = 0; i < 2; i++)
#pragma unroll
                for (int j = 0; j < 4; j++) {
                    mmaf16(c[i][2 * j],     ahi[i], bhi[j][0], bhi[j][1]);
                    mmaf16(c[i][2 * j + 1], ahi[i], bhi[j][2], bhi[j][3]);
                    mmaf16(c[i][2 * j],     ahi[i], blo[j][0], blo[j][1]);
                    mmaf16(c[i][2 * j + 1], ahi[i], blo[j][2], blo[j][3]);
                    mmaf16(c[i][2 * j],     alo[i], bhi[j][0], bhi[j][1]);
                    mmaf16(c[i][2 * j + 1], alo[i], bhi[j][2], bhi[j][3]);
                }
        }
        __syncthreads();
    }

    // epilogue
    int g = lane >> 2, tg = lane & 3;
    int zone = n0 >> 10, nb = n0 & 1023;
    const float* bp = (zone == 0) ? bq : (zone == 1) ? bk : bv;
#pragma unroll
    for (int i = 0; i < 2; i++) {
        int mlo = m0 + wm + i * 16 + g;
#pragma unroll
        for (int t = 0; t < 8; t++) {
            int n = nb + wn + t * 8 + tg * 2;
            float b0v = bp[n], b1v = bp[n + 1];
            int hh = n >> 6, hd = n & 63;
#pragma unroll
            for (int rr = 0; rr < 2; rr++) {
                int m = mlo + rr * 8, bb = m >> 11, s = m & 2047;
                float f0 = c[i][t][rr * 2] + b0v;
                float f1 = c[i][t][rr * 2 + 1] + b1v;
                __half h0 = __float2half_rn(f0), h1 = __float2half_rn(f1);
                __half l0 = __float2half_rn(f0 - __half2float(h0));
                __half l1 = __float2half_rn(f1 - __half2float(h1));
                if (zone < 2) {
                    __half* Oh = zone ? g_Khi : g_Qhi;
                    __half* Ol = zone ? g_Klo : g_Qlo;
                    size_t off = ((size_t)(bb * 16 + hh) * 2048 + s) * 64 + hd;
                    *(uint32_t*)(Oh + off) = packh2(h0, h1);
                    *(uint32_t*)(Ol + off) = packh2(l0, l1);
                } else {
                    size_t off = ((size_t)(bb * 16 + hh) * 64 + hd) * 2048 + s;
                    g_Vhi[off] = h0;        g_Vlo[off] = l0;
                    g_Vhi[off + 2048] = h1; g_Vlo[off + 2048] = l1;
                }
            }
        }
    }
}

// ---------------- flash attention (mma.sync fp16 split) ----------------
// smem: [0,8192) mask (pre-scaled); [8192,81920) KV double buffer.
#define AKV  8192
#define ATEN 9216                     // 64 * 72 * 2 B
#define ASTG (4 * ATEN)               // 36864
#define ASM  (AKV + 2 * ASTG)         // 81920

__global__ __launch_bounds__(256) void k_attn(const float* __restrict__ mask,
                                              float* __restrict__ out)
{
    extern __shared__ char sm[];
    uint32_t sb = s2u(sm);
    int tid = threadIdx.x, wid = tid >> 5, lane = tid & 31;
    int qt = blockIdx.x, h = blockIdx.y, b = blockIdx.z, bh = b * 16 + h;
    int wq = wid * 16;
    int g = lane >> 2, tg = lane & 3;
    int arow = lane & 15, asel = (lane >> 4) * 8;
    int q8 = lane >> 3, r8 = lane & 7;
    int brow = ((q8 >> 1) ? 8 : 0) + r8, bsel = (q8 & 1) * 8;

    const __half* Qh = g_Qhi + ((size_t)bh * 2048 + qt * 128) * 64;
    const __half* Ql = g_Qlo + ((size_t)bh * 2048 + qt * 128) * 64;
    const __half* Kh = g_Khi + (size_t)bh * 2048 * 64;
    const __half* Kl = g_Klo + (size_t)bh * 2048 * 64;
    const __half* Vh = g_Vhi + (size_t)bh * 64 * 2048;
    const __half* Vl = g_Vlo + (size_t)bh * 64 * 2048;

    // stage Q through KV buffer 0
#pragma unroll
    for (int t = 0; t < 8; t++) {
        int id = tid + t * 256;                     // 0..2047
        int tensor = id >> 10, within = id & 1023;
        int row = within >> 3, c8 = within & 7;
        const __half* src = (tensor ? Ql : Qh) + (size_t)row * 64 + c8 * 8;
        cpa16(sb + AKV + tensor * (2 * ATEN) + row * 144 + c8 * 16, src);
    }
    CP_COMMIT();
    float* msks = (float*)sm;
#pragma unroll
    for (int i = 0; i < 8; i++) {
        int col = tid + i * 256;
        msks[col] = mask[b * 2048 + col] * LOG2E + PSH;
    }
    CP_WAIT0();
    __syncthreads();

    uint32_t qhi[4][4], qlo[4][4];
#pragma unroll
    for (int kt = 0; kt < 4; kt++) {
        uint32_t ad = sb + AKV + ((wq + arow) * 72 + kt * 16 + asel) * 2;
        ldm4(qhi[kt], ad);
        ldm4(qlo[kt], ad + 2 * ATEN);
    }
    __syncthreads();

    auto load_kv = [&](int buf, int kt) {
#pragma unroll
        for (int t = 0; t < 8; t++) {
            int id = tid + t * 256;
            int tensor = id >> 9, within = id & 511;
            int row = within >> 3, c8 = within & 7;
            const __half* src;
            if (tensor == 0)      src = Kh + (size_t)(kt * 64 + row) * 64 + c8 * 8;
            else if (tensor == 1) src = Kl + (size_t)(kt * 64 + row) * 64 + c8 * 8;
            else if (tensor == 2) src = Vh + (size_t)row * 2048 + kt * 64 + c8 * 8;
            else                  src = Vl + (size_t)row * 2048 + kt * 64 + c8 * 8;
            cpa16(sb + AKV + buf * ASTG + tensor * ATEN + row * 144 + c8 * 16, src);
        }
        CP_COMMIT();
    };

    float ctx[8][4];
#pragma unroll
    for (int t = 0; t < 8; t++)
#pragma unroll
        for (int r = 0; r < 4; r++) ctx[t][r] = 0.0f;
    float li0 = 0.0f, li1 = 0.0f;

    load_kv(0, 0);
    for (int kt = 0; kt < 32; kt++) {
        if (kt + 1 < 32) { load_kv((kt + 1) & 1, kt + 1); CP_WAIT1(); }
        else CP_WAIT0();
        __syncthreads();
        uint32_t base = sb + AKV + (kt & 1) * ASTG;

        float sc[8][4];
#pragma unroll
        for (int t = 0; t < 8; t++)
#pragma unroll
            for (int r = 0; r < 4; r++) sc[t][r] = 0.0f;

#pragma unroll
        for (int kk = 0; kk < 4; kk++) {
            uint32_t khi[4][4], klo[4][4];
#pragma unroll
            for (int j = 0; j < 4; j++) {
                uint32_t kd = base + ((j * 16 + brow) * 72 + kk * 16 + bsel) * 2;
                ldm4(khi[j], kd);
                ldm4(klo[j], kd + ATEN);
            }
#pragma unroll
            for (int j = 0; j < 4; j++) {
                mmaf16(sc[2 * j],     qhi[kk], khi[j][0], khi[j][1]);
                mmaf16(sc[2 * j + 1], qhi[kk], khi[j][2], khi[j][3]);
                mmaf16(sc[2 * j],     qhi[kk], klo[j][0], klo[j][1]);
                mmaf16(sc[2 * j + 1], qhi[kk], klo[j][2], klo[j][3]);
                mmaf16(sc[2 * j],     qlo[kk], khi[j][0], khi[j][1]);
                mmaf16(sc[2 * j + 1], qlo[kk], khi[j][2], khi[j][3]);
            }
        }

        // softmax (no max subtraction; scaled by 2^PSH, cancels at normalize)
        uint32_t phi[4][4], plo[4][4];
#pragma unroll
        for (int t = 0; t < 8; t++) {
            int col = kt * 64 + t * 8 + tg * 2;
            float m0v = msks[col], m1v = msks[col + 1];
            float p00 = ex2(fmaf(sc[t][0], SC2, m0v));
            float p01 = ex2(fmaf(sc[t][1], SC2, m1v));
            float p10 = ex2(fmaf(sc[t][2], SC2, m0v));
            float p11 = ex2(fmaf(sc[t][3], SC2, m1v));
            li0 += p00 + p01;
            li1 += p10 + p11;
            __half a0 = __float2half_rn(p00), a1 = __float2half_rn(p01);
            __half a2 = __float2half_rn(p10), a3 = __float2half_rn(p11);
            int j = t >> 1, o = (t & 1) * 2;
            phi[j][o]     = packh2(a0, a1);
            phi[j][o + 1] = packh2(a2, a3);
            plo[j][o]     = packh2(__float2half_rn(p00 - __half2float(a0)),
                                   __float2half_rn(p01 - __half2float(a1)));
            plo[j][o + 1] = packh2(__float2half_rn(p10 - __half2float(a2)),
                                   __float2half_rn(p11 - __half2float(a3)));
        }

        // ctx += P @ V  (V^T staged: rows = hd, cols = kv)
#pragma unroll
        for (int j = 0; j < 4; j++) {
            uint32_t vhi[4][4], vlo[4][4];
#pragma unroll
            for (int n4 = 0; n4 < 4; n4++) {
                uint32_t vd = base + 2 * ATEN + ((n4 * 16 + brow) * 72 + j * 16 + bsel) * 2;
                ldm4(vhi[n4], vd);
                ldm4(vlo[n4], vd + ATEN);
            }
#pragma unroll
            for (int n4 = 0; n4 < 4; n4++) {
                mmaf16(ctx[2 * n4],     phi[j], vhi[n4][0], vhi[n4][1]);
                mmaf16(ctx[2 * n4 + 1], phi[j], vhi[n4][2], vhi[n4][3]);
                mmaf16(ctx[2 * n4],     phi[j], vlo[n4][0], vlo[n4][1]);
                mmaf16(ctx[2 * n4 + 1], phi[j], vlo[n4][2], vlo[n4][3]);
                mmaf16(ctx[2 * n4],     plo[j], vhi[n4][0], vhi[n4][1]);
                mmaf16(ctx[2 * n4 + 1], plo[j], vhi[n4][2], vhi[n4][3]);
            }
        }
        __syncthreads();
    }

    // row sums across the 4-lane group, normalize, write out
    li0 += __shfl_xor_sync(0xFFFFFFFFu, li0, 1);
    li0 += __shfl_xor_sync(0xFFFFFFFFu, li0, 2);
    li1 += __shfl_xor_sync(0xFFFFFFFFu, li1, 1);
    li1 += __shfl_xor_sync(0xFFFFFFFFu, li1, 2);
    float inv0 = 1.0f / li0, inv1 = 1.0f / li1;
    int s0 = qt * 128 + wq + g;
    float* o0 = out + ((size_t)(b * 2048 + s0)) * 1024 + h * 64;
    float* o1 = o0 + 8 * 1024;
#pragma unroll
    for (int t = 0; t < 8; t++) {
        int hd = t * 8 + tg * 2;
        float2 v0 = { ctx[t][0] * inv0, ctx[t][1] * inv0 };
        float2 v1 = { ctx[t][2] * inv1, ctx[t][3] * inv1 };
        *(float2*)(o0 + hd) = v0;
        *(float2*)(o1 + hd) = v1;
    }
}

// ---------------- launch ----------------
extern "C" void kernel_launch(void* const* d_in, const int* in_sizes, int n_in,
                              void* d_out, int out_size)
{
    const float* hs = (const float*)d_in[0];
    const float* mask = (const float*)d_in[1];
    const float* Wq = (const float*)d_in[2];
    const float* bq = (const float*)d_in[3];
    const float* Wk = (const float*)d_in[4];
    const float* bk = (const float*)d_in[5];
    const float* Wv = (const float*)d_in[6];
    const float* bv = (const float*)d_in[7];
    float* out = (float*)d_out;

    k_split_x<<<4096, 256>>>((const float4*)hs);
    k_transw<<<dim3(32, 32, 3), dim3(32, 8)>>>(Wq, Wk, Wv);

    cudaFuncSetAttribute(k_gemm, cudaFuncAttributeMaxDynamicSharedMemorySize, GSM);
    k_gemm<<<dim3(24, 32), 256, GSM>>>(bq, bk, bv);

    cudaFuncSetAttribute(k_attn, cudaFuncAttributeMaxDynamicSharedMemorySize, ASM);
    k_attn<<<dim3(16, 16, 2), 256, ASM>>>(mask, out);
    (void)in_sizes; (void)n_in; (void)out_size;
}

// round 5
// speedup vs baseline: 3.2545x; 1.1679x over previous
#include <cuda_runtime.h>
#include <cuda_fp16.h>
#include <cstdint>

#define LOG2E 1.4426950408889634f
#define SC2   0.18033688011112042f   // 0.125 * LOG2E
#define PSH   9.0f                   // prob scale 2^9 (cancels in normalization)

__device__ __forceinline__ uint32_t s2u(const void* p) {
    uint32_t a;
    asm("{ .reg .u64 t; cvta.to.shared.u64 t, %1; cvt.u32.u64 %0, t; }" : "=r"(a) : "l"(p));
    return a;
}
__device__ __forceinline__ void ldm4(uint32_t (&r)[4], uint32_t addr) {
    asm volatile("ldmatrix.sync.aligned.m8n8.x4.shared.b16 {%0,%1,%2,%3}, [%4];"
        : "=r"(r[0]), "=r"(r[1]), "=r"(r[2]), "=r"(r[3]) : "r"(addr));
}
__device__ __forceinline__ void mmaf16(float (&c)[4], const uint32_t (&a)[4],
                                       uint32_t b0, uint32_t b1) {
    asm volatile("mma.sync.aligned.m16n8k16.row.col.f32.f16.f16.f32 "
        "{%0,%1,%2,%3}, {%4,%5,%6,%7}, {%8,%9}, {%0,%1,%2,%3};"
        : "+f"(c[0]), "+f"(c[1]), "+f"(c[2]), "+f"(c[3])
        : "r"(a[0]), "r"(a[1]), "r"(a[2]), "r"(a[3]), "r"(b0), "r"(b1));
}
__device__ __forceinline__ void cpa16(uint32_t dst, const void* src) {
    asm volatile("cp.async.cg.shared.global [%0], [%1], 16;" :: "r"(dst), "l"(src));
}
#define CP_COMMIT() asm volatile("cp.async.commit_group;" ::: "memory")
#define CP_WAIT0()  asm volatile("cp.async.wait_group 0;" ::: "memory")
#define CP_WAIT1()  asm volatile("cp.async.wait_group 1;" ::: "memory")

__device__ __forceinline__ float ex2(float x) {
    float y; asm("ex2.approx.f32 %0, %1;" : "=f"(y) : "f"(x)); return y;
}
__device__ __forceinline__ uint32_t packh2(__half a, __half b) {
    __half2 t = __halves2half2(a, b);
    return *reinterpret_cast<uint32_t*>(&t);
}

// ---------------- device scratch (no cudaMalloc) ----------------
__device__ __align__(16) __half g_Xhi[4096 * 1024];
__device__ __align__(16) __half g_Xlo[4096 * 1024];
__device__ __align__(16) __half g_Wthi[3072 * 1024];
__device__ __align__(16) __half g_Wtlo[3072 * 1024];
__device__ __align__(16) __half g_Qhi[32 * 2048 * 64];
__device__ __align__(16) __half g_Qlo[32 * 2048 * 64];
__device__ __align__(16) __half g_Khi[32 * 2048 * 64];
__device__ __align__(16) __half g_Klo[32 * 2048 * 64];
__device__ __align__(16) __half g_Vhi[32 * 64 * 2048];  // transposed [bh][hd][s]
__device__ __align__(16) __half g_Vlo[32 * 64 * 2048];

// ---------------- prep ----------------
__global__ __launch_bounds__(256) void k_split_x(const float4* __restrict__ X) {
    int i = blockIdx.x * 256 + threadIdx.x;
    float4 v = X[i];
    __half h0 = __float2half_rn(v.x), h1 = __float2half_rn(v.y);
    __half h2 = __float2half_rn(v.z), h3 = __float2half_rn(v.w);
    ((uint32_t*)g_Xhi)[2 * i] = packh2(h0, h1);
    ((uint32_t*)g_Xhi)[2 * i + 1] = packh2(h2, h3);
    ((uint32_t*)g_Xlo)[2 * i] = packh2(__float2half_rn(v.x - __half2float(h0)),
                                       __float2half_rn(v.y - __half2float(h1)));
    ((uint32_t*)g_Xlo)[2 * i + 1] = packh2(__float2half_rn(v.z - __half2float(h2)),
                                           __float2half_rn(v.w - __half2float(h3)));
}

__global__ void k_transw(const float* __restrict__ Wq, const float* __restrict__ Wk,
                         const float* __restrict__ Wv) {
    __shared__ float t[32][33];
    int z = blockIdx.z;
    const float* W = (z == 0) ? Wq : (z == 1) ? Wk : Wv;
    int n0 = blockIdx.x * 32, k0 = blockIdx.y * 32;
    int tx = threadIdx.x, ty = threadIdx.y;
#pragma unroll
    for (int i = 0; i < 4; i++)
        t[ty + i * 8][tx] = W[(k0 + ty + i * 8) * 1024 + n0 + tx];
    __syncthreads();
#pragma unroll
    for (int i = 0; i < 4; i++) {
        int n = n0 + ty + i * 8, k = k0 + tx;
        float x = t[tx][ty + i * 8];
        __half hi = __float2half_rn(x);
        g_Wthi[(size_t)(z * 1024 + n) * 1024 + k] = hi;
        g_Wtlo[(size_t)(z * 1024 + n) * 1024 + k] =
            __float2half_rn(x - __half2float(hi));
    }
}

// ---------------- fused QKV GEMM (mma.sync fp16 split) ----------------
#define GSTR 40                       // halves per smem row (32 + 8 pad)
#define GTEN (128 * GSTR * 2)         // 10240 B per tensor
#define GSTG (4 * GTEN)               // 40960 B per stage
#define GSM  (2 * GSTG)               // 81920 B

__global__ __launch_bounds__(256, 2) void k_gemm(
    const float* __restrict__ bq, const float* __restrict__ bk,
    const float* __restrict__ bv)
{
    extern __shared__ char sm[];
    uint32_t sb = s2u(sm);
    int tid = threadIdx.x, wid = tid >> 5, lane = tid & 31;
    int n0 = blockIdx.x * 128, m0 = blockIdx.y * 128;
    int wm = (wid & 3) * 32, wn = (wid >> 2) * 64;

    const __half* s0p = g_Xhi + (size_t)m0 * 1024;
    const __half* s1p = g_Xlo + (size_t)m0 * 1024;
    const __half* s2p = g_Wthi + (size_t)n0 * 1024;
    const __half* s3p = g_Wtlo + (size_t)n0 * 1024;

    float c[2][8][4];
#pragma unroll
    for (int i = 0; i < 2; i++)
#pragma unroll
        for (int t = 0; t < 8; t++)
#pragma unroll
            for (int r = 0; r < 4; r++) c[i][t][r] = 0.0f;

    auto load_stage = [&](int buf, int k0) {
#pragma unroll
        for (int t = 0; t < 8; t++) {
            int id = tid + t * 256;                 // 0..2047
            int tensor = id >> 9, within = id & 511;
            int row = within >> 2, c4 = within & 3;
            const __half* src = (tensor == 0 ? s0p : tensor == 1 ? s1p :
                                 tensor == 2 ? s2p : s3p) +
                                (size_t)row * 1024 + k0 + c4 * 8;
            uint32_t dst = sb + buf * GSTG + tensor * GTEN + row * (GSTR * 2) + c4 * 16;
            cpa16(dst, src);
        }
        CP_COMMIT();
    };

    load_stage(0, 0);
    int arow = lane & 15, asel = (lane >> 4) * 8;
    int q8 = lane >> 3, r8 = lane & 7;
    int brow = ((q8 >> 1) ? 8 : 0) + r8, bsel = (q8 & 1) * 8;

    for (int kc = 0; kc < 32; kc++) {
        if (kc + 1 < 32) { load_stage((kc + 1) & 1, (kc + 1) * 32); CP_WAIT1(); }
        else CP_WAIT0();
        __syncthreads();
        uint32_t base = sb + (kc & 1) * GSTG;
#pragma unroll
        for (int ks = 0; ks < 2; ks++) {
            int koff = ks * 16;
            uint32_t ahi[2][4], alo[2][4];
#pragma unroll
            for (int i = 0; i < 2; i++) {
                uint32_t ad = base + ((wm + i * 16 + arow) * GSTR + koff + asel) * 2;
                ldm4(ahi[i], ad);
                ldm4(alo[i], ad + GTEN);
            }
#pragma unroll
            for (int j = 0; j < 4; j++) {
                uint32_t bhi[4], blo[4];
                uint32_t bd = base + 2 * GTEN + ((wn + j * 16 + brow) * GSTR + koff + bsel) * 2;
                ldm4(bhi, bd);
                ldm4(blo, bd + GTEN);
#pragma unroll
                for (int i = 0; i < 2; i++) {
                    mmaf16(c[i][2 * j],     ahi[i], bhi[0], bhi[1]);
                    mmaf16(c[i][2 * j + 1], ahi[i], bhi[2], bhi[3]);
                    mmaf16(c[i][2 * j],     ahi[i], blo[0], blo[1]);
                    mmaf16(c[i][2 * j + 1], ahi[i], blo[2], blo[3]);
                    mmaf16(c[i][2 * j],     alo[i], bhi[0], bhi[1]);
                    mmaf16(c[i][2 * j + 1], alo[i], bhi[2], bhi[3]);
                }
            }
        }
        __syncthreads();
    }

    // epilogue
    int g = lane >> 2, tg = lane & 3;
    int zone = n0 >> 10, nb = n0 & 1023;
    const float* bp = (zone == 0) ? bq : (zone == 1) ? bk : bv;
#pragma unroll
    for (int i = 0; i < 2; i++) {
        int mlo = m0 + wm + i * 16 + g;
#pragma unroll
        for (int t = 0; t < 8; t++) {
            int n = nb + wn + t * 8 + tg * 2;
            float b0v = bp[n], b1v = bp[n + 1];
            int hh = n >> 6, hd = n & 63;
#pragma unroll
            for (int rr = 0; rr < 2; rr++) {
                int m = mlo + rr * 8, bb = m >> 11, s = m & 2047;
                float f0 = c[i][t][rr * 2] + b0v;
                float f1 = c[i][t][rr * 2 + 1] + b1v;
                __half h0 = __float2half_rn(f0), h1 = __float2half_rn(f1);
                __half l0 = __float2half_rn(f0 - __half2float(h0));
                __half l1 = __float2half_rn(f1 - __half2float(h1));
                if (zone < 2) {
                    __half* Oh = zone ? g_Khi : g_Qhi;
                    __half* Ol = zone ? g_Klo : g_Qlo;
                    size_t off = ((size_t)(bb * 16 + hh) * 2048 + s) * 64 + hd;
                    *(uint32_t*)(Oh + off) = packh2(h0, h1);
                    *(uint32_t*)(Ol + off) = packh2(l0, l1);
                } else {
                    size_t off = ((size_t)(bb * 16 + hh) * 64 + hd) * 2048 + s;
                    g_Vhi[off] = h0;        g_Vlo[off] = l0;
                    g_Vhi[off + 2048] = h1; g_Vlo[off + 2048] = l1;
                }
            }
        }
    }
}

// ---------------- flash attention (mma.sync fp16 split) ----------------
#define AKV  8192
#define ATEN 9216                     // 64 * 72 * 2 B
#define ASTG (4 * ATEN)               // 36864
#define ASM  (AKV + 2 * ASTG)         // 81920

__global__ __launch_bounds__(256, 2) void k_attn(const float* __restrict__ mask,
                                                 float* __restrict__ out)
{
    extern __shared__ char sm[];
    uint32_t sb = s2u(sm);
    int tid = threadIdx.x, wid = tid >> 5, lane = tid & 31;
    int qt = blockIdx.x, h = blockIdx.y, b = blockIdx.z, bh = b * 16 + h;
    int wq = wid * 16;
    int g = lane >> 2, tg = lane & 3;
    int arow = lane & 15, asel = (lane >> 4) * 8;
    int q8 = lane >> 3, r8 = lane & 7;
    int brow = ((q8 >> 1) ? 8 : 0) + r8, bsel = (q8 & 1) * 8;

    const __half* Qh = g_Qhi + ((size_t)bh * 2048 + qt * 128) * 64;
    const __half* Ql = g_Qlo + ((size_t)bh * 2048 + qt * 128) * 64;
    const __half* Kh = g_Khi + (size_t)bh * 2048 * 64;
    const __half* Kl = g_Klo + (size_t)bh * 2048 * 64;
    const __half* Vh = g_Vhi + (size_t)bh * 64 * 2048;
    const __half* Vl = g_Vlo + (size_t)bh * 64 * 2048;

    // stage Q through KV buffer 0
#pragma unroll
    for (int t = 0; t < 8; t++) {
        int id = tid + t * 256;                     // 0..2047
        int tensor = id >> 10, within = id & 1023;
        int row = within >> 3, c8 = within & 7;
        const __half* src = (tensor ? Ql : Qh) + (size_t)row * 64 + c8 * 8;
        cpa16(sb + AKV + tensor * (2 * ATEN) + row * 144 + c8 * 16, src);
    }
    CP_COMMIT();
    float* msks = (float*)sm;
#pragma unroll
    for (int i = 0; i < 8; i++) {
        int col = tid + i * 256;
        msks[col] = mask[b * 2048 + col] * LOG2E + PSH;
    }
    CP_WAIT0();
    __syncthreads();

    uint32_t qhi[4][4], qlo[4][4];
#pragma unroll
    for (int kk = 0; kk < 4; kk++) {
        uint32_t ad = sb + AKV + ((wq + arow) * 72 + kk * 16 + asel) * 2;
        ldm4(qhi[kk], ad);
        ldm4(qlo[kk], ad + 2 * ATEN);
    }
    __syncthreads();

    auto load_kv = [&](int buf, int kt) {
#pragma unroll
        for (int t = 0; t < 8; t++) {
            int id = tid + t * 256;
            int tensor = id >> 9, within = id & 511;
            int row = within >> 3, c8 = within & 7;
            const __half* src;
            if (tensor == 0)      src = Kh + (size_t)(kt * 64 + row) * 64 + c8 * 8;
            else if (tensor == 1) src = Kl + (size_t)(kt * 64 + row) * 64 + c8 * 8;
            else if (tensor == 2) src = Vh + (size_t)row * 2048 + kt * 64 + c8 * 8;
            else                  src = Vl + (size_t)row * 2048 + kt * 64 + c8 * 8;
            cpa16(sb + AKV + buf * ASTG + tensor * ATEN + row * 144 + c8 * 16, src);
        }
        CP_COMMIT();
    };

    float ctx[8][4];
#pragma unroll
    for (int t = 0; t < 8; t++)
#pragma unroll
        for (int r = 0; r < 4; r++) ctx[t][r] = 0.0f;
    float li0 = 0.0f, li1 = 0.0f;

    load_kv(0, 0);
    for (int kt = 0; kt < 32; kt++) {
        if (kt + 1 < 32) { load_kv((kt + 1) & 1, kt + 1); CP_WAIT1(); }
        else CP_WAIT0();
        __syncthreads();
        uint32_t base = sb + AKV + (kt & 1) * ASTG;

        // process this 64-wide kv tile in 4 groups of 16 kv columns
#pragma unroll
        for (int jg = 0; jg < 4; jg++) {
            float sc[2][4];
#pragma unroll
            for (int t = 0; t < 2; t++)
#pragma unroll
                for (int r = 0; r < 4; r++) sc[t][r] = 0.0f;

#pragma unroll
            for (int kk = 0; kk < 4; kk++) {
                uint32_t khi[4], klo[4];
                uint32_t kd = base + ((jg * 16 + brow) * 72 + kk * 16 + bsel) * 2;
                ldm4(khi, kd);
                ldm4(klo, kd + ATEN);
                mmaf16(sc[0], qhi[kk], khi[0], khi[1]);
                mmaf16(sc[1], qhi[kk], khi[2], khi[3]);
                mmaf16(sc[0], qhi[kk], klo[0], klo[1]);
                mmaf16(sc[1], qhi[kk], klo[2], klo[3]);
                mmaf16(sc[0], qlo[kk], khi[0], khi[1]);
                mmaf16(sc[1], qlo[kk], khi[2], khi[3]);
            }

            // softmax for these 16 columns -> A-fragment P (hi + lo)
            uint32_t phi[4], plo[4];
#pragma unroll
            for (int t = 0; t < 2; t++) {
                int col = kt * 64 + jg * 16 + t * 8 + tg * 2;
                float m0v = msks[col], m1v = msks[col + 1];
                float p00 = ex2(fmaf(sc[t][0], SC2, m0v));
                float p01 = ex2(fmaf(sc[t][1], SC2, m1v));
                float p10 = ex2(fmaf(sc[t][2], SC2, m0v));
                float p11 = ex2(fmaf(sc[t][3], SC2, m1v));
                li0 += p00 + p01;
                li1 += p10 + p11;
                __half a0 = __float2half_rn(p00), a1 = __float2half_rn(p01);
                __half a2 = __float2half_rn(p10), a3 = __float2half_rn(p11);
                phi[t * 2]     = packh2(a0, a1);
                phi[t * 2 + 1] = packh2(a2, a3);
                plo[t * 2]     = packh2(__float2half_rn(p00 - __half2float(a0)),
                                        __float2half_rn(p01 - __half2float(a1)));
                plo[t * 2 + 1] = packh2(__float2half_rn(p10 - __half2float(a2)),
                                        __float2half_rn(p11 - __half2float(a3)));
            }

            // ctx += P(16 cols) @ V chunk
#pragma unroll
            for (int n4 = 0; n4 < 4; n4++) {
                uint32_t vhi[4], vlo[4];
                uint32_t vd = base + 2 * ATEN + ((n4 * 16 + brow) * 72 + jg * 16 + bsel) * 2;
                ldm4(vhi, vd);
                ldm4(vlo, vd + ATEN);
                mmaf16(ctx[2 * n4],     phi, vhi[0], vhi[1]);
                mmaf16(ctx[2 * n4 + 1], phi, vhi[2], vhi[3]);
                mmaf16(ctx[2 * n4],     phi, vlo[0], vlo[1]);
                mmaf16(ctx[2 * n4 + 1], phi, vlo[2], vlo[3]);
                mmaf16(ctx[2 * n4],     plo, vhi[0], vhi[1]);
                mmaf16(ctx[2 * n4 + 1], plo, vhi[2], vhi[3]);
            }
        }
        __syncthreads();
    }

    // row sums across the 4-lane group, normalize, write out
    li0 += __shfl_xor_sync(0xFFFFFFFFu, li0, 1);
    li0 += __shfl_xor_sync(0xFFFFFFFFu, li0, 2);
    li1 += __shfl_xor_sync(0xFFFFFFFFu, li1, 1);
    li1 += __shfl_xor_sync(0xFFFFFFFFu, li1, 2);
    float inv0 = 1.0f / li0, inv1 = 1.0f / li1;
    int s0 = qt * 128 + wq + g;
    float* o0 = out + ((size_t)(b * 2048 + s0)) * 1024 + h * 64;
    float* o1 = o0 + 8 * 1024;
#pragma unroll
    for (int t = 0; t < 8; t++) {
        int hd = t * 8 + tg * 2;
        float2 v0 = { ctx[t][0] * inv0, ctx[t][1] * inv0 };
        float2 v1 = { ctx[t][2] * inv1, ctx[t][3] * inv1 };
        *(float2*)(o0 + hd) = v0;
        *(float2*)(o1 + hd) = v1;
    }
}

// ---------------- launch ----------------
extern "C" void kernel_launch(void* const* d_in, const int* in_sizes, int n_in,
                              void* d_out, int out_size)
{
    const float* hs = (const float*)d_in[0];
    const float* mask = (const float*)d_in[1];
    const float* Wq = (const float*)d_in[2];
    const float* bq = (const float*)d_in[3];
    const float* Wk = (const float*)d_in[4];
    const float* bk = (const float*)d_in[5];
    const float* Wv = (const float*)d_in[6];
    const float* bv = (const float*)d_in[7];
    float* out = (float*)d_out;

    k_split_x<<<4096, 256>>>((const float4*)hs);
    k_transw<<<dim3(32, 32, 3), dim3(32, 8)>>>(Wq, Wk, Wv);

    cudaFuncSetAttribute(k_gemm, cudaFuncAttributeMaxDynamicSharedMemorySize, GSM);
    k_gemm<<<dim3(24, 32), 256, GSM>>>(bq, bk, bv);

    cudaFuncSetAttribute(k_attn, cudaFuncAttributeMaxDynamicSharedMemorySize, ASM);
    k_attn<<<dim3(16, 16, 2), 256, ASM>>>(mask, out);
    (void)in_sizes; (void)n_in; (void)out_size;
}

// round 6
// speedup vs baseline: 3.3808x; 1.0388x over previous
#include <cuda_runtime.h>
#include <cuda_fp16.h>
#include <cstdint>

#define LOG2E 1.4426950408889634f
#define SC2   0.18033688011112042f   // 0.125 * LOG2E
#define PSH   9.0f                   // prob scale 2^9 (cancels in normalization)

__device__ __forceinline__ uint32_t s2u(const void* p) {
    uint32_t a;
    asm("{ .reg .u64 t; cvta.to.shared.u64 t, %1; cvt.u32.u64 %0, t; }" : "=r"(a) : "l"(p));
    return a;
}
__device__ __forceinline__ void ldm4(uint32_t (&r)[4], uint32_t addr) {
    asm volatile("ldmatrix.sync.aligned.m8n8.x4.shared.b16 {%0,%1,%2,%3}, [%4];"
        : "=r"(r[0]), "=r"(r[1]), "=r"(r[2]), "=r"(r[3]) : "r"(addr));
}
__device__ __forceinline__ void mmaf16(float (&c)[4], const uint32_t (&a)[4],
                                       uint32_t b0, uint32_t b1) {
    asm volatile("mma.sync.aligned.m16n8k16.row.col.f32.f16.f16.f32 "
        "{%0,%1,%2,%3}, {%4,%5,%6,%7}, {%8,%9}, {%0,%1,%2,%3};"
        : "+f"(c[0]), "+f"(c[1]), "+f"(c[2]), "+f"(c[3])
        : "r"(a[0]), "r"(a[1]), "r"(a[2]), "r"(a[3]), "r"(b0), "r"(b1));
}
__device__ __forceinline__ void cpa16(uint32_t dst, const void* src) {
    asm volatile("cp.async.cg.shared.global [%0], [%1], 16;" :: "r"(dst), "l"(src));
}
#define CP_COMMIT() asm volatile("cp.async.commit_group;" ::: "memory")
#define CP_WAIT0()  asm volatile("cp.async.wait_group 0;" ::: "memory")
#define CP_WAIT1()  asm volatile("cp.async.wait_group 1;" ::: "memory")

__device__ __forceinline__ float ex2(float x) {
    float y; asm("ex2.approx.f32 %0, %1;" : "=f"(y) : "f"(x)); return y;
}
__device__ __forceinline__ uint32_t packh2(__half a, __half b) {
    __half2 t = __halves2half2(a, b);
    return *reinterpret_cast<uint32_t*>(&t);
}

// ---------------- device scratch (no cudaMalloc) ----------------
__device__ __align__(16) __half g_Xhi[4096 * 1024];
__device__ __align__(16) __half g_Xlo[4096 * 1024];
__device__ __align__(16) __half g_Wthi[3072 * 1024];
__device__ __align__(16) __half g_Wtlo[3072 * 1024];
__device__ __align__(16) __half g_Qhi[32 * 2048 * 64];
__device__ __align__(16) __half g_Khi[32 * 2048 * 64];
__device__ __align__(16) __half g_Klo[32 * 2048 * 64];
__device__ __align__(16) __half g_Vhi[32 * 64 * 2048];  // transposed [bh][hd][s]
__device__ __align__(16) __half g_Vlo[32 * 64 * 2048];

// ---------------- prep ----------------
__global__ __launch_bounds__(256) void k_split_x(const float4* __restrict__ X) {
    int i = blockIdx.x * 256 + threadIdx.x;
    float4 v = X[i];
    __half h0 = __float2half_rn(v.x), h1 = __float2half_rn(v.y);
    __half h2 = __float2half_rn(v.z), h3 = __float2half_rn(v.w);
    ((uint32_t*)g_Xhi)[2 * i] = packh2(h0, h1);
    ((uint32_t*)g_Xhi)[2 * i + 1] = packh2(h2, h3);
    ((uint32_t*)g_Xlo)[2 * i] = packh2(__float2half_rn(v.x - __half2float(h0)),
                                       __float2half_rn(v.y - __half2float(h1)));
    ((uint32_t*)g_Xlo)[2 * i + 1] = packh2(__float2half_rn(v.z - __half2float(h2)),
                                           __float2half_rn(v.w - __half2float(h3)));
}

__global__ void k_transw(const float* __restrict__ Wq, const float* __restrict__ Wk,
                         const float* __restrict__ Wv) {
    __shared__ float t[32][33];
    int z = blockIdx.z;
    const float* W = (z == 0) ? Wq : (z == 1) ? Wk : Wv;
    int n0 = blockIdx.x * 32, k0 = blockIdx.y * 32;
    int tx = threadIdx.x, ty = threadIdx.y;
#pragma unroll
    for (int i = 0; i < 4; i++)
        t[ty + i * 8][tx] = W[(k0 + ty + i * 8) * 1024 + n0 + tx];
    __syncthreads();
#pragma unroll
    for (int i = 0; i < 4; i++) {
        int n = n0 + ty + i * 8, k = k0 + tx;
        float x = t[tx][ty + i * 8];
        __half hi = __float2half_rn(x);
        g_Wthi[(size_t)(z * 1024 + n) * 1024 + k] = hi;
        g_Wtlo[(size_t)(z * 1024 + n) * 1024 + k] =
            __float2half_rn(x - __half2float(hi));
    }
}

// ---------------- fused QKV GEMM (mma.sync fp16 split) ----------------
// Q,K zones: 2-pass (Xhi*Whi + Xhi*Wlo); V zone: 3-pass (+ Xlo*Whi).
#define GSTR 40                       // halves per smem row (32 + 8 pad)
#define GTEN (128 * GSTR * 2)         // 10240 B per tensor
#define GSTG (4 * GTEN)               // 40960 B per stage
#define GSM  (2 * GSTG)               // 81920 B

__global__ __launch_bounds__(256, 2) void k_gemm(
    const float* __restrict__ bq, const float* __restrict__ bk,
    const float* __restrict__ bv)
{
    extern __shared__ char sm[];
    uint32_t sb = s2u(sm);
    int tid = threadIdx.x, wid = tid >> 5, lane = tid & 31;
    int n0 = blockIdx.x * 128, m0 = blockIdx.y * 128;
    int wm = (wid & 3) * 32, wn = (wid >> 2) * 64;
    const bool three = (n0 >= 2048);   // V zone gets the 3rd pass

    const __half* s0p = g_Xhi + (size_t)m0 * 1024;
    const __half* s1p = g_Xlo + (size_t)m0 * 1024;
    const __half* s2p = g_Wthi + (size_t)n0 * 1024;
    const __half* s3p = g_Wtlo + (size_t)n0 * 1024;

    float c[2][8][4];
#pragma unroll
    for (int i = 0; i < 2; i++)
#pragma unroll
        for (int t = 0; t < 8; t++)
#pragma unroll
            for (int r = 0; r < 4; r++) c[i][t][r] = 0.0f;

    auto load_stage = [&](int buf, int k0) {
#pragma unroll
        for (int t = 0; t < 8; t++) {
            int id = tid + t * 256;                 // 0..2047
            int tensor = id >> 9, within = id & 511;
            int row = within >> 2, c4 = within & 3;
            const __half* src = (tensor == 0 ? s0p : tensor == 1 ? s1p :
                                 tensor == 2 ? s2p : s3p) +
                                (size_t)row * 1024 + k0 + c4 * 8;
            uint32_t dst = sb + buf * GSTG + tensor * GTEN + row * (GSTR * 2) + c4 * 16;
            cpa16(dst, src);
        }
        CP_COMMIT();
    };

    load_stage(0, 0);
    int arow = lane & 15, asel = (lane >> 4) * 8;
    int q8 = lane >> 3, r8 = lane & 7;
    int brow = ((q8 >> 1) ? 8 : 0) + r8, bsel = (q8 & 1) * 8;

    for (int kc = 0; kc < 32; kc++) {
        if (kc + 1 < 32) { load_stage((kc + 1) & 1, (kc + 1) * 32); CP_WAIT1(); }
        else CP_WAIT0();
        __syncthreads();
        uint32_t base = sb + (kc & 1) * GSTG;
#pragma unroll
        for (int ks = 0; ks < 2; ks++) {
            int koff = ks * 16;
            uint32_t ahi[2][4], alo[2][4];
#pragma unroll
            for (int i = 0; i < 2; i++) {
                uint32_t ad = base + ((wm + i * 16 + arow) * GSTR + koff + asel) * 2;
                ldm4(ahi[i], ad);
                if (three) ldm4(alo[i], ad + GTEN);
            }
#pragma unroll
            for (int j = 0; j < 4; j++) {
                uint32_t bhi[4], blo[4];
                uint32_t bd = base + 2 * GTEN + ((wn + j * 16 + brow) * GSTR + koff + bsel) * 2;
                ldm4(bhi, bd);
                ldm4(blo, bd + GTEN);
#pragma unroll
                for (int i = 0; i < 2; i++) {
                    mmaf16(c[i][2 * j],     ahi[i], bhi[0], bhi[1]);
                    mmaf16(c[i][2 * j + 1], ahi[i], bhi[2], bhi[3]);
                    mmaf16(c[i][2 * j],     ahi[i], blo[0], blo[1]);
                    mmaf16(c[i][2 * j + 1], ahi[i], blo[2], blo[3]);
                    if (three) {
                        mmaf16(c[i][2 * j],     alo[i], bhi[0], bhi[1]);
                        mmaf16(c[i][2 * j + 1], alo[i], bhi[2], bhi[3]);
                    }
                }
            }
        }
        __syncthreads();
    }

    // epilogue
    int g = lane >> 2, tg = lane & 3;
    int zone = n0 >> 10, nb = n0 & 1023;
    const float* bp = (zone == 0) ? bq : (zone == 1) ? bk : bv;
#pragma unroll
    for (int i = 0; i < 2; i++) {
        int mlo = m0 + wm + i * 16 + g;
#pragma unroll
        for (int t = 0; t < 8; t++) {
            int n = nb + wn + t * 8 + tg * 2;
            float b0v = bp[n], b1v = bp[n + 1];
            int hh = n >> 6, hd = n & 63;
#pragma unroll
            for (int rr = 0; rr < 2; rr++) {
                int m = mlo + rr * 8, bb = m >> 11, s = m & 2047;
                float f0 = c[i][t][rr * 2] + b0v;
                float f1 = c[i][t][rr * 2 + 1] + b1v;
                __half h0 = __float2half_rn(f0), h1 = __float2half_rn(f1);
                if (zone == 0) {
                    size_t off = ((size_t)(bb * 16 + hh) * 2048 + s) * 64 + hd;
                    *(uint32_t*)(g_Qhi + off) = packh2(h0, h1);
                } else if (zone == 1) {
                    __half l0 = __float2half_rn(f0 - __half2float(h0));
                    __half l1 = __float2half_rn(f1 - __half2float(h1));
                    size_t off = ((size_t)(bb * 16 + hh) * 2048 + s) * 64 + hd;
                    *(uint32_t*)(g_Khi + off) = packh2(h0, h1);
                    *(uint32_t*)(g_Klo + off) = packh2(l0, l1);
                } else {
                    __half l0 = __float2half_rn(f0 - __half2float(h0));
                    __half l1 = __float2half_rn(f1 - __half2float(h1));
                    size_t off = ((size_t)(bb * 16 + hh) * 64 + hd) * 2048 + s;
                    g_Vhi[off] = h0;        g_Vlo[off] = l0;
                    g_Vhi[off + 2048] = h1; g_Vlo[off + 2048] = l1;
                }
            }
        }
    }
}

// ---------------- flash attention (mma.sync fp16 split) ----------------
// QK^T: 2-pass (qhi*khi + qhi*klo). PV: 3-pass (phi*vhi + phi*vlo + plo*vhi).
#define AKV  8192
#define ATEN 9216                     // 64 * 72 * 2 B
#define ASTG (4 * ATEN)               // 36864
#define ASM  (AKV + 2 * ASTG)         // 81920

__global__ __launch_bounds__(256, 2) void k_attn(const float* __restrict__ mask,
                                                 float* __restrict__ out)
{
    extern __shared__ char sm[];
    uint32_t sb = s2u(sm);
    int tid = threadIdx.x, wid = tid >> 5, lane = tid & 31;
    int qt = blockIdx.x, h = blockIdx.y, b = blockIdx.z, bh = b * 16 + h;
    int wq = wid * 16;
    int g = lane >> 2, tg = lane & 3;
    int arow = lane & 15, asel = (lane >> 4) * 8;
    int q8 = lane >> 3, r8 = lane & 7;
    int brow = ((q8 >> 1) ? 8 : 0) + r8, bsel = (q8 & 1) * 8;

    const __half* Qh = g_Qhi + ((size_t)bh * 2048 + qt * 128) * 64;
    const __half* Kh = g_Khi + (size_t)bh * 2048 * 64;
    const __half* Kl = g_Klo + (size_t)bh * 2048 * 64;
    const __half* Vh = g_Vhi + (size_t)bh * 64 * 2048;
    const __half* Vl = g_Vlo + (size_t)bh * 64 * 2048;

    // stage Q (hi only) through KV buffer 0
#pragma unroll
    for (int t = 0; t < 4; t++) {
        int id = tid + t * 256;                     // 0..1023
        int row = id >> 3, c8 = id & 7;
        cpa16(sb + AKV + row * 144 + c8 * 16, Qh + (size_t)row * 64 + c8 * 8);
    }
    CP_COMMIT();
    float* msks = (float*)sm;
#pragma unroll
    for (int i = 0; i < 8; i++) {
        int col = tid + i * 256;
        msks[col] = mask[b * 2048 + col] * LOG2E + PSH;
    }
    CP_WAIT0();
    __syncthreads();

    uint32_t qhi[4][4];
#pragma unroll
    for (int kk = 0; kk < 4; kk++) {
        uint32_t ad = sb + AKV + ((wq + arow) * 72 + kk * 16 + asel) * 2;
        ldm4(qhi[kk], ad);
    }
    __syncthreads();

    auto load_kv = [&](int buf, int kt) {
#pragma unroll
        for (int t = 0; t < 8; t++) {
            int id = tid + t * 256;
            int tensor = id >> 9, within = id & 511;
            int row = within >> 3, c8 = within & 7;
            const __half* src;
            if (tensor == 0)      src = Kh + (size_t)(kt * 64 + row) * 64 + c8 * 8;
            else if (tensor == 1) src = Kl + (size_t)(kt * 64 + row) * 64 + c8 * 8;
            else if (tensor == 2) src = Vh + (size_t)row * 2048 + kt * 64 + c8 * 8;
            else                  src = Vl + (size_t)row * 2048 + kt * 64 + c8 * 8;
            cpa16(sb + AKV + buf * ASTG + tensor * ATEN + row * 144 + c8 * 16, src);
        }
        CP_COMMIT();
    };

    float ctx[8][4];
#pragma unroll
    for (int t = 0; t < 8; t++)
#pragma unroll
        for (int r = 0; r < 4; r++) ctx[t][r] = 0.0f;
    float li0 = 0.0f, li1 = 0.0f;

    load_kv(0, 0);
    for (int kt = 0; kt < 32; kt++) {
        if (kt + 1 < 32) { load_kv((kt + 1) & 1, kt + 1); CP_WAIT1(); }
        else CP_WAIT0();
        __syncthreads();
        uint32_t base = sb + AKV + (kt & 1) * ASTG;

        // process this 64-wide kv tile in 4 groups of 16 kv columns
#pragma unroll
        for (int jg = 0; jg < 4; jg++) {
            float sc[2][4];
#pragma unroll
            for (int t = 0; t < 2; t++)
#pragma unroll
                for (int r = 0; r < 4; r++) sc[t][r] = 0.0f;

#pragma unroll
            for (int kk = 0; kk < 4; kk++) {
                uint32_t khi[4], klo[4];
                uint32_t kd = base + ((jg * 16 + brow) * 72 + kk * 16 + bsel) * 2;
                ldm4(khi, kd);
                ldm4(klo, kd + ATEN);
                mmaf16(sc[0], qhi[kk], khi[0], khi[1]);
                mmaf16(sc[1], qhi[kk], khi[2], khi[3]);
                mmaf16(sc[0], qhi[kk], klo[0], klo[1]);
                mmaf16(sc[1], qhi[kk], klo[2], klo[3]);
            }

            // softmax for these 16 columns -> A-fragment P (hi + lo)
            uint32_t phi[4], plo[4];
#pragma unroll
            for (int t = 0; t < 2; t++) {
                int col = kt * 64 + jg * 16 + t * 8 + tg * 2;
                float m0v = msks[col], m1v = msks[col + 1];
                float p00 = ex2(fmaf(sc[t][0], SC2, m0v));
                float p01 = ex2(fmaf(sc[t][1], SC2, m1v));
                float p10 = ex2(fmaf(sc[t][2], SC2, m0v));
                float p11 = ex2(fmaf(sc[t][3], SC2, m1v));
                li0 += p00 + p01;
                li1 += p10 + p11;
                __half a0 = __float2half_rn(p00), a1 = __float2half_rn(p01);
                __half a2 = __float2half_rn(p10), a3 = __float2half_rn(p11);
                phi[t * 2]     = packh2(a0, a1);
                phi[t * 2 + 1] = packh2(a2, a3);
                plo[t * 2]     = packh2(__float2half_rn(p00 - __half2float(a0)),
                                        __float2half_rn(p01 - __half2float(a1)));
                plo[t * 2 + 1] = packh2(__float2half_rn(p10 - __half2float(a2)),
                                        __float2half_rn(p11 - __half2float(a3)));
            }

            // ctx += P(16 cols) @ V chunk  (3-pass)
#pragma unroll
            for (int n4 = 0; n4 < 4; n4++) {
                uint32_t vhi[4], vlo[4];
                uint32_t vd = base + 2 * ATEN + ((n4 * 16 + brow) * 72 + jg * 16 + bsel) * 2;
                ldm4(vhi, vd);
                ldm4(vlo, vd + ATEN);
                mmaf16(ctx[2 * n4],     phi, vhi[0], vhi[1]);
                mmaf16(ctx[2 * n4 + 1], phi, vhi[2], vhi[3]);
                mmaf16(ctx[2 * n4],     phi, vlo[0], vlo[1]);
                mmaf16(ctx[2 * n4 + 1], phi, vlo[2], vlo[3]);
                mmaf16(ctx[2 * n4],     plo, vhi[0], vhi[1]);
                mmaf16(ctx[2 * n4 + 1], plo, vhi[2], vhi[3]);
            }
        }
        __syncthreads();
    }

    // row sums across the 4-lane group, normalize, write out
    li0 += __shfl_xor_sync(0xFFFFFFFFu, li0, 1);
    li0 += __shfl_xor_sync(0xFFFFFFFFu, li0, 2);
    li1 += __shfl_xor_sync(0xFFFFFFFFu, li1, 1);
    li1 += __shfl_xor_sync(0xFFFFFFFFu, li1, 2);
    float inv0 = 1.0f / li0, inv1 = 1.0f / li1;
    int s0 = qt * 128 + wq + g;
    float* o0 = out + ((size_t)(b * 2048 + s0)) * 1024 + h * 64;
    float* o1 = o0 + 8 * 1024;
#pragma unroll
    for (int t = 0; t < 8; t++) {
        int hd = t * 8 + tg * 2;
        float2 v0 = { ctx[t][0] * inv0, ctx[t][1] * inv0 };
        float2 v1 = { ctx[t][2] * inv1, ctx[t][3] * inv1 };
        *(float2*)(o0 + hd) = v0;
        *(float2*)(o1 + hd) = v1;
    }
}

// ---------------- launch ----------------
extern "C" void kernel_launch(void* const* d_in, const int* in_sizes, int n_in,
                              void* d_out, int out_size)
{
    const float* hs = (const float*)d_in[0];
    const float* mask = (const float*)d_in[1];
    const float* Wq = (const float*)d_in[2];
    const float* bq = (const float*)d_in[3];
    const float* Wk = (const float*)d_in[4];
    const float* bk = (const float*)d_in[5];
    const float* Wv = (const float*)d_in[6];
    const float* bv = (const float*)d_in[7];
    float* out = (float*)d_out;

    k_split_x<<<4096, 256>>>((const float4*)hs);
    k_transw<<<dim3(32, 32, 3), dim3(32, 8)>>>(Wq, Wk, Wv);

    cudaFuncSetAttribute(k_gemm, cudaFuncAttributeMaxDynamicSharedMemorySize, GSM);
    k_gemm<<<dim3(24, 32), 256, GSM>>>(bq, bk, bv);

    cudaFuncSetAttribute(k_attn, cudaFuncAttributeMaxDynamicSharedMemorySize, ASM);
    k_attn<<<dim3(16, 16, 2), 256, ASM>>>(mask, out);
    (void)in_sizes; (void)n_in; (void)out_size;
}